// round 11
// baseline (speedup 1.0000x reference)
#include <cuda_runtime.h>

// Problem constants (fixed by the reference)
#define NN        10000
#define CH        16
#define BATCH     8
#define E_EDGES   320000           // = 512 * 625
#define WSTRIDE   5120000          // floats between weight[i] planes
#define OUTPLANE  160000
#define NRES      625              // residue classes: n mod 625
#define FLATS     512              // (d,c) pairs per node
#define XSLOTS    5                // x ring slots (pair-barrier scheme)
#define XSLOTF    1024             // x slot: 32 rows * 32 floats (4 KB)
#define WSLOTF    256              // w slot per warp: 2n*4i*32 (1 KB)
#define NODE_OFF  (NRES * 8)

#define CP_A16(dst, src) \
    asm volatile("cp.async.cg.shared.global [%0], [%1], 16;" :: "r"(dst), "l"(src))
#define CP_A16Z(dst, src, sz) \
    asm volatile("cp.async.cg.shared.global [%0], [%1], 16, %2;" \
                 :: "r"(dst), "l"(src), "r"(sz))
#define CP_COMMIT() asm volatile("cp.async.commit_group;")
#define CP_WAIT1()  asm volatile("cp.async.wait_group 1;")

// ---------------------------------------------------------------------------
// Single fused kernel. Block (256 thr, 8 warps) = residue class r.
// Warp w computes nA = r + 625*w, nB = r + 625*(w+8).
// Stage s covers flats 32s..32s+31 (d = 2s+dpar, lane = 16*dpar + c).
//  - edges: block detects int64/int32 and loads its own 512 indices (no prep).
//  - x: gathered DIRECTLY from x via cp.async (transposed row == 8 native
//    16B chunks of x); src==NN pad handled by ignore-src zero-fill.
//  - x ring: 5 slots, block-shared; w rings: 4-deep per-warp private.
//  - stages processed in PAIRS: one wait_group+syncthreads per 2 stages.
// smem 54 KB, <=64 regs -> 4 blocks (32 warps)/SM.
// ---------------------------------------------------------------------------
__global__ __launch_bounds__(256, 4)
void lcg_main(const float* __restrict__ x, const void* __restrict__ edges,
              const float* __restrict__ W, float* __restrict__ out) {
    __shared__ __align__(16) float xr[XSLOTS][XSLOTF];   // 20480 B
    __shared__ __align__(16) float wr[8][4][WSLOTF];     // 32768 B
    __shared__ int se[FLATS];                            // 2048 B
    __shared__ int s_is32;
    const int r    = blockIdx.x;
    const int tid  = threadIdx.x;
    const int w    = tid >> 5;
    const int lane = tid & 31;

    // ---- dtype detection: int64 layout -> all odd int32 words are zero
    //      high-words (values <= 10000). Samples in-bounds for BOTH layouts.
    if (tid == 0) s_is32 = 0;
    __syncthreads();
    if (tid < 64) {
        int slot = 2 * (tid * 2499) + 1;      // max 314875 < 320000
        if (((const int*)edges)[slot] != 0) atomicOr(&s_is32, 1);
    }
    __syncthreads();
    if (s_is32) {
        const int* e = (const int*)edges + r * FLATS;
        se[tid] = e[tid];  se[tid + 256] = e[tid + 256];
    } else {
        const long long* e = (const long long*)edges + r * FLATS;
        se[tid] = (int)e[tid];  se[tid + 256] = (int)e[tid + 256];
    }
    __syncthreads();

    // ---- x-ring fill geometry: row jx = tid>>3, batch-chunk gx = tid&7
    const int jx = tid >> 3;
    const int gx = tid & 7;
    const unsigned xrb = (unsigned)__cvta_generic_to_shared(&xr[0][0]);
    const unsigned xd  = (unsigned)((jx * 32 + 4 * (gx ^ (jx & 7))) * 4);
    const float* xsrc = x + (size_t)gx * (NN * 4);       // + src*4 floats

    // ---- w-ring fill geometry: this warp's two nodes, plane ii, chunk gg
    const int ii = lane >> 3, gg = lane & 7;
    const float* wsrcA = W + (size_t)ii * WSTRIDE
                           + (size_t)(r + NRES * w) * FLATS + 4 * gg;
    const float* wsrcB = wsrcA + (size_t)NODE_OFF * FLATS;
    const unsigned wrb = (unsigned)__cvta_generic_to_shared(&wr[w][0][0]);
    const unsigned wdA = (unsigned)((ii * 32 + 4 * gg) * 4);
    const unsigned wdB = wdA + 128 * 4;

#define XFILL(n, xs) do {                                                  \
        int e0 = se[32 * (n) + jx];                                        \
        unsigned sz = (e0 < NN) ? 16u : 0u;                                \
        int e0c = (e0 < NN) ? e0 : 0;                                      \
        CP_A16Z(xrb + (unsigned)((xs) * XSLOTF * 4) + xd,                  \
                xsrc + (size_t)e0c * 4, sz);                               \
    } while (0)

#define WFILL(n) do {                                                      \
        const unsigned ws = (unsigned)(((n) & 3) * WSLOTF * 4);            \
        CP_A16(wrb + ws + wdA, wsrcA + 32 * (n));                          \
        CP_A16(wrb + ws + wdB, wsrcB + 32 * (n));                          \
    } while (0)

    // ---- prologue: stages 0..2 in flight (3 commit groups)
#pragma unroll
    for (int p = 0; p < 3; ++p) {
        XFILL(p, p);
        WFILL(p);
        CP_COMMIT();
    }

    // ---- main loop: 8 pairs of stages
    float accA[BATCH], accB[BATCH];
#pragma unroll
    for (int b = 0; b < BATCH; ++b) { accA[b] = 0.0f; accB[b] = 0.0f; }

    const int swz = lane & 7;

#define STAGE_COMPUTE(s, xs) do {                                          \
        const float* wp = &wr[w][(s) & 3][lane];                           \
        const float a0 = wp[0],   a1 = wp[32],  a2 = wp[64],  a3 = wp[96]; \
        const float b0 = wp[128], b1 = wp[160], b2 = wp[192], b3 = wp[224];\
        const float4* __restrict__ rp =                                    \
            reinterpret_cast<const float4*>(&xr[(xs)][lane * 32]);         \
        _Pragma("unroll")                                                  \
        for (int b = 0; b < BATCH; ++b) {                                  \
            float4 v = rp[b ^ swz];                                        \
            accA[b] += v.x * a0 + v.y * a1 + v.z * a2 + v.w * a3;          \
            accB[b] += v.x * b0 + v.y * b1 + v.z * b2 + v.w * b3;          \
        }                                                                  \
    } while (0)

#pragma unroll
    for (int p = 0; p < 8; ++p) {
        const int s0 = 2 * p;
        // committed = 3 + 2p groups; pending<=1 => groups s0 and s0+1 landed
        CP_WAIT1();
        __syncthreads();       // all x chunks of s0, s0+1 visible; older reads done

        STAGE_COMPUTE(s0,     (s0) % XSLOTS);
        STAGE_COMPUTE(s0 + 1, (s0 + 1) % XSLOTS);

        // refill stages s0+3, s0+4: their x slots held s0-2, s0-1 (drained by
        // the barrier above); their w slots held s0-1, s0 (own-warp order).
        const int n0 = s0 + 3, n1 = s0 + 4;
        if (n0 < 16) { XFILL(n0, (s0 + 3) % XSLOTS); WFILL(n0); }
        CP_COMMIT();
        if (n1 < 16) { XFILL(n1, (s0 + 4) % XSLOTS); WFILL(n1); }
        CP_COMMIT();           // exactly 2 commits per pair (static counting)
    }

    // ---- combine d-parities (lane <-> lane^16), write out
#pragma unroll
    for (int b = 0; b < BATCH; ++b) {
        accA[b] += __shfl_xor_sync(0xffffffffu, accA[b], 16);
        accB[b] += __shfl_xor_sync(0xffffffffu, accB[b], 16);
    }

    const int nA = r + NRES * w;
    const int nB = nA + NODE_OFF;
    const int c    = lane & 15;
    const int half = lane >> 4;            // 0 -> batches 0..3, 1 -> 4..7
#pragma unroll
    for (int k = 0; k < 4; ++k) {
        const int b = half * 4 + k;
        out[b * OUTPLANE + nA * CH + c] = half ? accA[k + 4] : accA[k];
        out[b * OUTPLANE + nB * CH + c] = half ? accB[k + 4] : accB[k];
    }
#undef XFILL
#undef WFILL
#undef STAGE_COMPUTE
}

// ---------------------------------------------------------------------------
// Launch: single kernel, no prep.
// ---------------------------------------------------------------------------
extern "C" void kernel_launch(void* const* d_in, const int* in_sizes, int n_in,
                              void* d_out, int out_size) {
    const float* x     = (const float*)d_in[0];   // (8,10000,4) f32
    const void*  edges = d_in[1];                 // (320000,) int64/int32
    const float* W     = (const float*)d_in[2];   // (4,320000,16) f32
    float*       out   = (float*)d_out;           // (8,10000,16) f32
    (void)in_sizes; (void)n_in; (void)out_size;

    lcg_main<<<NRES, 256>>>(x, edges, W, out);
}

// round 12
// speedup vs baseline: 1.0112x; 1.0112x over previous
#include <cuda_runtime.h>

// Problem constants (fixed by the reference)
#define NN        10000
#define CH        16
#define BATCH     8
#define E_EDGES   320000           // = 512 * 625
#define WSTRIDE   5120000          // floats between weight[i] planes
#define OUTPLANE  160000
#define NRES      625              // residue classes: n mod 625
#define FLATS     512              // (d,c) pairs per node
#define DEPTH     4
#define XSLOTF    1024             // x slot: 32 rows * 32 floats (4 KB)
#define WSLOTF    256              // w slot per warp: 2n*4i*32 (1 KB)
#define NODE_OFF  (NRES * 8)

#define CP_A16(dst, src) \
    asm volatile("cp.async.cg.shared.global [%0], [%1], 16;" :: "r"(dst), "l"(src))
#define CP_A16Z(dst, src, sz) \
    asm volatile("cp.async.cg.shared.global [%0], [%1], 16, %2;" \
                 :: "r"(dst), "l"(src), "r"(sz))
#define CP_COMMIT() asm volatile("cp.async.commit_group;")
#define CP_WAIT2()  asm volatile("cp.async.wait_group 2;")

// ---------------------------------------------------------------------------
// Single fused kernel (R10 loop structure + R11 fusion).
// Block (256 thr, 8 warps) = residue class r; warp w computes
// nA = r + 625*w, nB = r + 625*(w+8).
// Stage s covers flats 32s..32s+31 (d = 2s+dpar, lane = 16*dpar + c).
//  - edges: block detects int64/int32, loads its own 512 indices into smem.
//  - x: gathered DIRECTLY from x via cp.async (chunk gx of row src is the
//    native 16B x[gx, src, 0..3]); src==NN pad -> ignore-src zero-fill.
//  - x ring: 4 slots block-shared; w rings: 4-deep per-warp private.
//  - per-stage: one wait_group(2) + one __syncthreads (3-stage lookahead).
// smem 51 KB, <=64 regs -> 4 blocks (32 warps)/SM.
// ---------------------------------------------------------------------------
__global__ __launch_bounds__(256, 4)
void lcg_main(const float* __restrict__ x, const void* __restrict__ edges,
              const float* __restrict__ W, float* __restrict__ out) {
    __shared__ __align__(16) float xr[DEPTH][XSLOTF];    // 16384 B
    __shared__ __align__(16) float wr[8][DEPTH][WSLOTF]; // 32768 B
    __shared__ int se[FLATS];                            // 2048 B
    __shared__ int s_is32;
    const int r    = blockIdx.x;
    const int tid  = threadIdx.x;
    const int w    = tid >> 5;
    const int lane = tid & 31;

    // ---- dtype detection: int64 layout -> odd int32 words are zero
    //      high-words (values <= 10000). Samples in-bounds for BOTH layouts.
    if (tid == 0) s_is32 = 0;
    __syncthreads();
    if (tid < 64) {
        int slot = 2 * (tid * 2499) + 1;      // max 314875 < 320000
        if (((const int*)edges)[slot] != 0) atomicOr(&s_is32, 1);
    }
    __syncthreads();
    if (s_is32) {
        const int* e = (const int*)edges + r * FLATS;
        se[tid] = e[tid];  se[tid + 256] = e[tid + 256];
    } else {
        const long long* e = (const long long*)edges + r * FLATS;
        se[tid] = (int)e[tid];  se[tid + 256] = (int)e[tid + 256];
    }
    __syncthreads();

    // ---- x-ring fill geometry: row jx = tid>>3, batch-chunk gx = tid&7
    const int jx = tid >> 3;
    const int gx = tid & 7;
    const unsigned xrb = (unsigned)__cvta_generic_to_shared(&xr[0][0]);
    const unsigned xd  = (unsigned)((jx * 32 + 4 * (gx ^ (jx & 7))) * 4);
    const float* xsrc = x + (size_t)gx * (NN * 4);       // + src*4 floats

    // ---- w-ring fill geometry: this warp's two nodes, plane ii, chunk gg
    const int ii = lane >> 3, gg = lane & 7;
    const float* wsrcA = W + (size_t)ii * WSTRIDE
                           + (size_t)(r + NRES * w) * FLATS + 4 * gg;
    const float* wsrcB = wsrcA + (size_t)NODE_OFF * FLATS;
    const unsigned wrb = (unsigned)__cvta_generic_to_shared(&wr[w][0][0]);
    const unsigned wdA = (unsigned)((ii * 32 + 4 * gg) * 4);
    const unsigned wdB = wdA + 128 * 4;

#define XFILL(n) do {                                                      \
        int e0 = se[32 * (n) + jx];                                        \
        unsigned sz = (e0 < NN) ? 16u : 0u;                                \
        int e0c = (e0 < NN) ? e0 : 0;                                      \
        CP_A16Z(xrb + (unsigned)(((n) & 3) * XSLOTF * 4) + xd,             \
                xsrc + (size_t)e0c * 4, sz);                               \
    } while (0)

#define WFILL(n) do {                                                      \
        const unsigned ws = (unsigned)(((n) & 3) * WSLOTF * 4);            \
        CP_A16(wrb + ws + wdA, wsrcA + 32 * (n));                          \
        CP_A16(wrb + ws + wdB, wsrcB + 32 * (n));                          \
    } while (0)

    // ---- prologue: stages 0..2 in flight
#pragma unroll
    for (int p = 0; p < DEPTH - 1; ++p) {
        XFILL(p);
        WFILL(p);
        CP_COMMIT();
    }

    // ---- main loop: one stage at a time (3-stage lookahead)
    float accA[BATCH], accB[BATCH];
#pragma unroll
    for (int b = 0; b < BATCH; ++b) { accA[b] = 0.0f; accB[b] = 0.0f; }

    const int swz = lane & 7;

#pragma unroll
    for (int s = 0; s < 16; ++s) {
        CP_WAIT2();            // groups through stage s landed
        __syncthreads();       // all x chunks visible; stage s-1 reads done

        const int slot = s & 3;

        const float* wp = &wr[w][slot][lane];
        const float a0 = wp[0],   a1 = wp[32],  a2 = wp[64],  a3 = wp[96];
        const float b0 = wp[128], b1 = wp[160], b2 = wp[192], b3 = wp[224];

        const float4* __restrict__ rp =
            reinterpret_cast<const float4*>(&xr[slot][lane * 32]);
#pragma unroll
        for (int b = 0; b < BATCH; ++b) {
            float4 v = rp[b ^ swz];        // logical batch b (swizzled)
            accA[b] += v.x * a0 + v.y * a1 + v.z * a2 + v.w * a3;
            accB[b] += v.x * b0 + v.y * b1 + v.z * b2 + v.w * b3;
        }

        // refill slot (s-1)&3: barrier above proves all reads of it finished
        const int nx = s + DEPTH - 1;
        if (nx < 16) {
            XFILL(nx);
            WFILL(nx);
        }
        CP_COMMIT();           // exactly one commit per stage
    }

    // ---- combine d-parities (lane <-> lane^16), write out
#pragma unroll
    for (int b = 0; b < BATCH; ++b) {
        accA[b] += __shfl_xor_sync(0xffffffffu, accA[b], 16);
        accB[b] += __shfl_xor_sync(0xffffffffu, accB[b], 16);
    }

    const int nA = r + NRES * w;
    const int nB = nA + NODE_OFF;
    const int c    = lane & 15;
    const int half = lane >> 4;            // 0 -> batches 0..3, 1 -> 4..7
#pragma unroll
    for (int k = 0; k < 4; ++k) {
        const int b = half * 4 + k;
        out[b * OUTPLANE + nA * CH + c] = half ? accA[k + 4] : accA[k];
        out[b * OUTPLANE + nB * CH + c] = half ? accB[k + 4] : accB[k];
    }
#undef XFILL
#undef WFILL
}

// ---------------------------------------------------------------------------
// Launch: single kernel, no prep.
// ---------------------------------------------------------------------------
extern "C" void kernel_launch(void* const* d_in, const int* in_sizes, int n_in,
                              void* d_out, int out_size) {
    const float* x     = (const float*)d_in[0];   // (8,10000,4) f32
    const void*  edges = d_in[1];                 // (320000,) int64/int32
    const float* W     = (const float*)d_in[2];   // (4,320000,16) f32
    float*       out   = (float*)d_out;           // (8,10000,16) f32
    (void)in_sizes; (void)n_in; (void)out_size;

    lcg_main<<<NRES, 256>>>(x, edges, W, out);
}

// round 13
// speedup vs baseline: 1.1068x; 1.0945x over previous
#include <cuda_runtime.h>

// Problem constants (fixed by the reference)
#define NN        10000
#define CH        16
#define BATCH     8
#define E_EDGES   320000           // = 512 * 625
#define WSTRIDE   5120000          // floats between weight[i] planes
#define OUTPLANE  160000
#define NRES      625              // residue classes: n mod 625
#define FLATS     512              // (d,c) pairs per node
#define DEPTH     4
#define XSLOTF    1024             // x slot: 32 rows * 32 floats (4 KB)
#define WSLOTF    256              // w slot per warp: 2n*4i*32 (1 KB)
#define NODE_OFF  (NRES * 8)

// Scratch (allocation-free: __device__ globals)
__device__ float g_xT[(NN + 1) * 32];   // [node][b*4+i], row NN = zeros
__device__ int   g_e32[E_EDGES];

#define CP_A16(dst, src) \
    asm volatile("cp.async.cg.shared.global [%0], [%1], 16;" :: "r"(dst), "l"(src))
#define CP_COMMIT() asm volatile("cp.async.commit_group;")
#define CP_WAIT2()  asm volatile("cp.async.wait_group 2;")

// ---------------------------------------------------------------------------
// Prep (optimized): both sides coalesced, high MLP.
//  - transpose: thread = node j; 8 independent float4 reads (one per batch,
//    coalesced across lanes), one contiguous 128B row write.
//  - edges: vectorized int4 / longlong2 narrowing, grid-stride.
// ---------------------------------------------------------------------------
__global__ void prep_kernel(const float* __restrict__ x,
                            const void*  __restrict__ edges) {
    __shared__ int s_is32;
    const int t = threadIdx.x;
    if (t == 0) s_is32 = 0;
    __syncthreads();
    if (t < 64) {
        int slot = 2 * (t * 2499) + 1;    // odd int32 word; in-bounds both layouts
        if (((const int*)edges)[slot] != 0) atomicOr(&s_is32, 1);
    }
    __syncthreads();
    const bool is32 = (s_is32 != 0);

    const int gtid = blockIdx.x * blockDim.x + t;
    const int nth  = gridDim.x * blockDim.x;

    // ---- edge narrowing (vectorized)
    if (is32) {
        const int4* e = (const int4*)edges;
        int4* o = (int4*)g_e32;
        for (int j = gtid; j < E_EDGES / 4; j += nth) o[j] = e[j];
    } else {
        const longlong2* e = (const longlong2*)edges;
        int2* o = (int2*)g_e32;
        for (int j = gtid; j < E_EDGES / 2; j += nth) {
            longlong2 v = e[j];
            o[j] = make_int2((int)v.x, (int)v.y);
        }
    }

    // ---- transpose: node j -> full 128B row of g_xT
    for (int j = gtid; j <= NN; j += nth) {
        float4 row[8];
        if (j < NN) {
#pragma unroll
            for (int b = 0; b < 8; ++b)
                row[b] = *(const float4*)(x + (size_t)b * (NN * 4) + (size_t)j * 4);
        } else {
#pragma unroll
            for (int b = 0; b < 8; ++b) row[b] = make_float4(0.f, 0.f, 0.f, 0.f);
        }
        float4* dst = (float4*)(g_xT + (size_t)j * 32);
#pragma unroll
        for (int b = 0; b < 8; ++b) dst[b] = row[b];
    }
}

// ---------------------------------------------------------------------------
// Main (identical to the proven R10 kernel, 24.2us measured).
// Block (256 thr, 8 warps) = residue class r; warp w computes
// nA = r + 625*w, nB = r + 625*(w+8).
// Stage s covers flats 32s..32s+31 (d = 2s+dpar, lane = 16*dpar + c).
// ---------------------------------------------------------------------------
__global__ __launch_bounds__(256, 4)
void lcg_main(const float* __restrict__ W, float* __restrict__ out) {
    __shared__ __align__(16) float xr[DEPTH][XSLOTF];    // 16384 B
    __shared__ __align__(16) float wr[8][DEPTH][WSLOTF]; // 32768 B
    __shared__ int se[FLATS];                            // 2048 B
    const int r    = blockIdx.x;
    const int tid  = threadIdx.x;
    const int w    = tid >> 5;
    const int lane = tid & 31;

    // ---- preload this residue class's edge list (coalesced, once)
    se[tid]       = g_e32[r * FLATS + tid];
    se[tid + 256] = g_e32[r * FLATS + tid + 256];
    __syncthreads();

    // ---- x-ring fill geometry: row jx = tid>>3, chunk gx = tid&7
    const int jx = tid >> 3;
    const int gx = tid & 7;
    const unsigned xrb = (unsigned)__cvta_generic_to_shared(&xr[0][0]);
    const unsigned xd  = (unsigned)((jx * 32 + 4 * (gx ^ (jx & 7))) * 4);

    // ---- w-ring fill geometry: this warp's two nodes, plane ii, chunk gg
    const int ii = lane >> 3, gg = lane & 7;
    const float* wsrcA = W + (size_t)ii * WSTRIDE
                           + (size_t)(r + NRES * w) * FLATS + 4 * gg;
    const float* wsrcB = wsrcA + (size_t)NODE_OFF * FLATS;
    const unsigned wrb = (unsigned)__cvta_generic_to_shared(&wr[w][0][0]);
    const unsigned wdA = (unsigned)((ii * 32 + 4 * gg) * 4);
    const unsigned wdB = wdA + 128 * 4;

#define XFILL(n) do {                                                      \
        int e0 = se[32 * (n) + jx];                                        \
        CP_A16(xrb + (unsigned)(((n) & 3) * XSLOTF * 4) + xd,              \
               g_xT + (size_t)e0 * 32 + 4 * gx);                           \
    } while (0)

#define WFILL(n) do {                                                      \
        const unsigned ws = (unsigned)(((n) & 3) * WSLOTF * 4);            \
        CP_A16(wrb + ws + wdA, wsrcA + 32 * (n));                          \
        CP_A16(wrb + ws + wdB, wsrcB + 32 * (n));                          \
    } while (0)

    // ---- prologue: stages 0..2 in flight
#pragma unroll
    for (int p = 0; p < DEPTH - 1; ++p) {
        XFILL(p);
        WFILL(p);
        CP_COMMIT();
    }

    // ---- main loop
    float accA[BATCH], accB[BATCH];
#pragma unroll
    for (int b = 0; b < BATCH; ++b) { accA[b] = 0.0f; accB[b] = 0.0f; }

    const int swz = lane & 7;

#pragma unroll
    for (int s = 0; s < 16; ++s) {
        CP_WAIT2();            // groups through stage s landed
        __syncthreads();       // all x chunks visible; stage s-1 reads done

        const int slot = s & 3;

        const float* wp = &wr[w][slot][lane];
        const float a0 = wp[0],   a1 = wp[32],  a2 = wp[64],  a3 = wp[96];
        const float b0 = wp[128], b1 = wp[160], b2 = wp[192], b3 = wp[224];

        const float4* __restrict__ rp =
            reinterpret_cast<const float4*>(&xr[slot][lane * 32]);
#pragma unroll
        for (int b = 0; b < BATCH; ++b) {
            float4 v = rp[b ^ swz];        // logical batch b (swizzled)
            accA[b] += v.x * a0 + v.y * a1 + v.z * a2 + v.w * a3;
            accB[b] += v.x * b0 + v.y * b1 + v.z * b2 + v.w * b3;
        }

        // refill slot (s-1)&3: barrier above proves all reads of it finished
        const int nx = s + DEPTH - 1;
        if (nx < 16) {
            XFILL(nx);
            WFILL(nx);
        }
        CP_COMMIT();           // exactly one commit per stage
    }

    // ---- combine d-parities (lane <-> lane^16), write out
#pragma unroll
    for (int b = 0; b < BATCH; ++b) {
        accA[b] += __shfl_xor_sync(0xffffffffu, accA[b], 16);
        accB[b] += __shfl_xor_sync(0xffffffffu, accB[b], 16);
    }

    const int nA = r + NRES * w;
    const int nB = nA + NODE_OFF;
    const int c    = lane & 15;
    const int half = lane >> 4;            // 0 -> batches 0..3, 1 -> 4..7
#pragma unroll
    for (int k = 0; k < 4; ++k) {
        const int b = half * 4 + k;
        out[b * OUTPLANE + nA * CH + c] = half ? accA[k + 4] : accA[k];
        out[b * OUTPLANE + nB * CH + c] = half ? accB[k + 4] : accB[k];
    }
#undef XFILL
#undef WFILL
}

// ---------------------------------------------------------------------------
// Launch
// ---------------------------------------------------------------------------
extern "C" void kernel_launch(void* const* d_in, const int* in_sizes, int n_in,
                              void* d_out, int out_size) {
    const float* x     = (const float*)d_in[0];   // (8,10000,4) f32
    const void*  edges = d_in[1];                 // (320000,) int64/int32
    const float* W     = (const float*)d_in[2];   // (4,320000,16) f32
    float*       out   = (float*)d_out;           // (8,10000,16) f32
    (void)in_sizes; (void)n_in; (void)out_size;

    prep_kernel<<<160, 256>>>(x, edges);
    lcg_main<<<NRES, 256>>>(W, out);
}

// round 14
// speedup vs baseline: 1.1733x; 1.0601x over previous
#include <cuda_runtime.h>

// Problem constants (fixed by the reference)
#define NN        10000
#define CH        16
#define BATCH     8
#define E_EDGES   320000           // = 512 * 625
#define WSTRIDE   5120000          // floats between weight[i] planes
#define OUTPLANE  160000
#define NRES      625              // residue classes: n mod 625
#define FLATS     512              // (d,c) pairs per node
#define DEPTH     4
#define XSLOTF    1024             // x slot: 32 rows * 32 floats (4 KB)
#define WSLOTF    256              // w slot per warp: 2n*4i*32 (1 KB)
#define NODE_OFF  (NRES * 8)

// Scratch (allocation-free: __device__ globals)
__device__ float g_xT[(NN + 1) * 32];   // [node][b*4+i], row NN = zeros
__device__ int   g_e32[E_EDGES];

#define CP_A16(dst, src) \
    asm volatile("cp.async.cg.shared.global [%0], [%1], 16;" :: "r"(dst), "l"(src))
#define CP_COMMIT() asm volatile("cp.async.commit_group;")
#define CP_WAIT2()  asm volatile("cp.async.wait_group 2;")

// ---------------------------------------------------------------------------
// Prep (max parallelism): one thread per (node, batch) -> 1 LDG.128 + 1
// STG.128, depth-1 dependence chain; edges narrowed with vector loads.
// grid = 313 blocks * 256 thr = 80128 threads.
// ---------------------------------------------------------------------------
__global__ void prep_kernel(const float* __restrict__ x,
                            const void*  __restrict__ edges) {
    __shared__ int s_is32;
    const int t = threadIdx.x;
    if (t == 0) s_is32 = 0;
    __syncthreads();
    if (t < 64) {
        int slot = 2 * (t * 2499) + 1;    // odd int32 word; in-bounds both layouts
        if (((const int*)edges)[slot] != 0) atomicOr(&s_is32, 1);
    }
    __syncthreads();
    const bool is32 = (s_is32 != 0);

    const int gt  = blockIdx.x * blockDim.x + t;
    const int nth = gridDim.x * blockDim.x;

    // ---- transpose: task = (node j, batch b); j == NN writes the zero pad row
    {
        const int j = gt >> 3;
        const int b = gt & 7;
        if (j <= NN) {
            float4 v = make_float4(0.f, 0.f, 0.f, 0.f);
            if (j < NN)
                v = *(const float4*)(x + (size_t)b * (NN * 4) + (size_t)j * 4);
            *(float4*)(g_xT + (size_t)j * 32 + b * 4) = v;
        }
    }

    // ---- edge narrowing (vectorized, 1-2 iterations per thread)
    if (is32) {
        const int4* e = (const int4*)edges;
        int4* o = (int4*)g_e32;
        for (int j = gt; j < E_EDGES / 4; j += nth) o[j] = e[j];
    } else {
        const longlong2* e = (const longlong2*)edges;
        int2* o = (int2*)g_e32;
        for (int j = gt; j < E_EDGES / 2; j += nth) {
            longlong2 v = e[j];
            o[j] = make_int2((int)v.x, (int)v.y);
        }
    }
}

// ---------------------------------------------------------------------------
// Main (byte-identical to the proven R13 kernel, 23.2us measured).
// Block (256 thr, 8 warps) = residue class r; warp w computes
// nA = r + 625*w, nB = r + 625*(w+8).
// Stage s covers flats 32s..32s+31 (d = 2s+dpar, lane = 16*dpar + c).
// ---------------------------------------------------------------------------
__global__ __launch_bounds__(256, 4)
void lcg_main(const float* __restrict__ W, float* __restrict__ out) {
    __shared__ __align__(16) float xr[DEPTH][XSLOTF];    // 16384 B
    __shared__ __align__(16) float wr[8][DEPTH][WSLOTF]; // 32768 B
    __shared__ int se[FLATS];                            // 2048 B
    const int r    = blockIdx.x;
    const int tid  = threadIdx.x;
    const int w    = tid >> 5;
    const int lane = tid & 31;

    // ---- preload this residue class's edge list (coalesced, once)
    se[tid]       = g_e32[r * FLATS + tid];
    se[tid + 256] = g_e32[r * FLATS + tid + 256];
    __syncthreads();

    // ---- x-ring fill geometry: row jx = tid>>3, chunk gx = tid&7
    const int jx = tid >> 3;
    const int gx = tid & 7;
    const unsigned xrb = (unsigned)__cvta_generic_to_shared(&xr[0][0]);
    const unsigned xd  = (unsigned)((jx * 32 + 4 * (gx ^ (jx & 7))) * 4);

    // ---- w-ring fill geometry: this warp's two nodes, plane ii, chunk gg
    const int ii = lane >> 3, gg = lane & 7;
    const float* wsrcA = W + (size_t)ii * WSTRIDE
                           + (size_t)(r + NRES * w) * FLATS + 4 * gg;
    const float* wsrcB = wsrcA + (size_t)NODE_OFF * FLATS;
    const unsigned wrb = (unsigned)__cvta_generic_to_shared(&wr[w][0][0]);
    const unsigned wdA = (unsigned)((ii * 32 + 4 * gg) * 4);
    const unsigned wdB = wdA + 128 * 4;

#define XFILL(n) do {                                                      \
        int e0 = se[32 * (n) + jx];                                        \
        CP_A16(xrb + (unsigned)(((n) & 3) * XSLOTF * 4) + xd,              \
               g_xT + (size_t)e0 * 32 + 4 * gx);                           \
    } while (0)

#define WFILL(n) do {                                                      \
        const unsigned ws = (unsigned)(((n) & 3) * WSLOTF * 4);            \
        CP_A16(wrb + ws + wdA, wsrcA + 32 * (n));                          \
        CP_A16(wrb + ws + wdB, wsrcB + 32 * (n));                          \
    } while (0)

    // ---- prologue: stages 0..2 in flight
#pragma unroll
    for (int p = 0; p < DEPTH - 1; ++p) {
        XFILL(p);
        WFILL(p);
        CP_COMMIT();
    }

    // ---- main loop
    float accA[BATCH], accB[BATCH];
#pragma unroll
    for (int b = 0; b < BATCH; ++b) { accA[b] = 0.0f; accB[b] = 0.0f; }

    const int swz = lane & 7;

#pragma unroll
    for (int s = 0; s < 16; ++s) {
        CP_WAIT2();            // groups through stage s landed
        __syncthreads();       // all x chunks visible; stage s-1 reads done

        const int slot = s & 3;

        const float* wp = &wr[w][slot][lane];
        const float a0 = wp[0],   a1 = wp[32],  a2 = wp[64],  a3 = wp[96];
        const float b0 = wp[128], b1 = wp[160], b2 = wp[192], b3 = wp[224];

        const float4* __restrict__ rp =
            reinterpret_cast<const float4*>(&xr[slot][lane * 32]);
#pragma unroll
        for (int b = 0; b < BATCH; ++b) {
            float4 v = rp[b ^ swz];        // logical batch b (swizzled)
            accA[b] += v.x * a0 + v.y * a1 + v.z * a2 + v.w * a3;
            accB[b] += v.x * b0 + v.y * b1 + v.z * b2 + v.w * b3;
        }

        // refill slot (s-1)&3: barrier above proves all reads of it finished
        const int nx = s + DEPTH - 1;
        if (nx < 16) {
            XFILL(nx);
            WFILL(nx);
        }
        CP_COMMIT();           // exactly one commit per stage
    }

    // ---- combine d-parities (lane <-> lane^16), write out
#pragma unroll
    for (int b = 0; b < BATCH; ++b) {
        accA[b] += __shfl_xor_sync(0xffffffffu, accA[b], 16);
        accB[b] += __shfl_xor_sync(0xffffffffu, accB[b], 16);
    }

    const int nA = r + NRES * w;
    const int nB = nA + NODE_OFF;
    const int c    = lane & 15;
    const int half = lane >> 4;            // 0 -> batches 0..3, 1 -> 4..7
#pragma unroll
    for (int k = 0; k < 4; ++k) {
        const int b = half * 4 + k;
        out[b * OUTPLANE + nA * CH + c] = half ? accA[k + 4] : accA[k];
        out[b * OUTPLANE + nB * CH + c] = half ? accB[k + 4] : accB[k];
    }
#undef XFILL
#undef WFILL
}

// ---------------------------------------------------------------------------
// Launch
// ---------------------------------------------------------------------------
extern "C" void kernel_launch(void* const* d_in, const int* in_sizes, int n_in,
                              void* d_out, int out_size) {
    const float* x     = (const float*)d_in[0];   // (8,10000,4) f32
    const void*  edges = d_in[1];                 // (320000,) int64/int32
    const float* W     = (const float*)d_in[2];   // (4,320000,16) f32
    float*       out   = (float*)d_out;           // (8,10000,16) f32
    (void)in_sizes; (void)n_in; (void)out_size;

    prep_kernel<<<313, 256>>>(x, edges);
    lcg_main<<<NRES, 256>>>(W, out);
}